// round 6
// baseline (speedup 1.0000x reference)
#include <cuda_runtime.h>

#define Nn   16000
#define Ee   48000
#define Ff   32000
#define Gg   32
#define Dd   64
#define NBUMP 32
#define HIDN  256
#define NCLS  10
#define STRIP 512

#define NODE_W ((Nn + STRIP - 1) / STRIP)   // 32
#define EDGE_W ((Ee + STRIP - 1) / STRIP)   // 94
#define FACE_W ((Ff + STRIP - 1) / STRIP)   // 63
#define TOT_W  (NODE_W + EDGE_W + FACE_W)   // 189

// ---------------- scratch (static device globals; no allocation) ----------------
__device__ float d_nh[Dd * Nn];          // direction-major node heights
__device__ int   d_gbid[Nn];
__device__ int   d_es0[Ee], d_es1[Ee], d_eg[Ee];
__device__ float d_esw[Ee];
__device__ int   d_fs0[Ff], d_fs1[Ff], d_fs2[Ff], d_fg[Ff];
__device__ float d_fsw[Ff];
__device__ int   d_ncnt[Gg], d_ecnt[Gg], d_fcnt[Gg];
__device__ int   d_ecur[Gg], d_fcur[Gg];
__device__ int   d_netc[Gg];
__device__ float d_accS[Gg * NBUMP * Dd];  // signed tanh sums

// ---------------- kernels ----------------

__global__ void zero_kernel() {
    int i = blockIdx.x * blockDim.x + threadIdx.x;
    if (i < Gg * NBUMP * Dd) d_accS[i] = 0.f;
    if (i < Gg) { d_ncnt[i] = 0; d_ecnt[i] = 0; d_fcnt[i] = 0; }
}

__global__ void p1_kernel(const int* __restrict__ bid) {
    int n = blockIdx.x * blockDim.x + threadIdx.x;
    if (n >= Nn) return;
    int g = bid[n];
    d_gbid[n] = g;
    atomicAdd(&d_ncnt[g], 1);
}

__global__ void nh_kernel(const float* __restrict__ x,
                          const float* __restrict__ nw,
                          const float* __restrict__ v) {
    __shared__ float sv[3 * Dd];
    if (threadIdx.x < 3 * Dd) sv[threadIdx.x] = v[threadIdx.x];
    __syncthreads();
    int n = blockIdx.x * blockDim.x + threadIdx.x;
    if (n >= Nn) return;
    float x0 = x[3 * n], x1 = x[3 * n + 1], x2 = x[3 * n + 2];
    float w = nw[n];
    #pragma unroll 8
    for (int d = 0; d < Dd; d++) {
        d_nh[d * Nn + n] = w * (x0 * sv[d] + x1 * sv[Dd + d] + x2 * sv[2 * Dd + d]);
    }
}

__global__ void hist_ef(const int* __restrict__ ei,
                        const int* __restrict__ fc) {
    int i = blockIdx.x * blockDim.x + threadIdx.x;
    if (i < Ee) {
        int e0 = ei[i];
        atomicAdd(&d_ecnt[d_gbid[e0]], 1);
    } else if (i < Ee + Ff) {
        int j = i - Ee;
        int f0 = fc[j];
        atomicAdd(&d_fcnt[d_gbid[f0]], 1);
    }
}

__global__ void scan_kernel() {
    if (threadIdx.x == 0 && blockIdx.x == 0) {
        int ea = 0, fa = 0;
        for (int g = 0; g < Gg; g++) {
            d_ecur[g] = ea; ea += d_ecnt[g];
            d_fcur[g] = fa; fa += d_fcnt[g];
            d_netc[g] = d_ncnt[g] - d_ecnt[g] + d_fcnt[g];
        }
    }
}

__global__ void scatter_ef(const int* __restrict__ ei,
                           const float* __restrict__ ew,
                           const int* __restrict__ fc,
                           const float* __restrict__ fw) {
    int i = blockIdx.x * blockDim.x + threadIdx.x;
    if (i < Ee) {
        int e0 = ei[i];
        int e1 = ei[Ee + i];
        int g = d_gbid[e0];
        int pos = atomicAdd(&d_ecur[g], 1);
        d_es0[pos] = e0; d_es1[pos] = e1; d_esw[pos] = ew[i]; d_eg[pos] = g;
    } else if (i < Ee + Ff) {
        int j = i - Ee;
        int f0 = fc[j];
        int f1 = fc[Ff + j];
        int f2 = fc[2 * Ff + j];
        int g = d_gbid[f0];
        int pos = atomicAdd(&d_fcur[g], 1);
        d_fs0[pos] = f0; d_fs1[pos] = f1; d_fs2[pos] = f2; d_fsw[pos] = fw[j]; d_fg[pos] = g;
    }
}

__device__ __forceinline__ float tanha(float z) {
    float r;
    asm("tanh.approx.f32 %0, %1;" : "=f"(r) : "f"(z));
    return r;
}

// lane = bump index; broadcast element heights; register accumulation per (g, bump, d)
__global__ void __launch_bounds__(256) main_kernel() {
    const int d    = blockIdx.y;
    const int warp = blockIdx.x * (blockDim.x >> 5) + (threadIdx.x >> 5);
    const int lane = threadIdx.x & 31;
    if (warp >= TOT_W) return;

    int stream, w;
    if (warp < NODE_W)               { stream = 0; w = warp; }
    else if (warp < NODE_W + EDGE_W) { stream = 1; w = warp - NODE_W; }
    else                             { stream = 2; w = warp - NODE_W - EDGE_W; }

    const int cnt = (stream == 0) ? Nn : (stream == 1) ? Ee : Ff;
    const int begin = w * STRIP;
    const int end   = min(begin + STRIP, cnt);
    if (begin >= end) return;

    const float* __restrict__ nhd = d_nh + d * Nn;
    // tanh argument: 50*(lin[b] - h); lin[b] = -1 + 2b/31
    const float cl   = 50.f * (-1.f + (2.f / 31.f) * (float)lane);
    const float sign = (stream == 1) ? -1.f : 1.f;

    float acc = 0.f;
    int gcur = -1;

    for (int base = begin; base < end; base += 32) {
        int idx = base + lane;
        float hs; int g;
        if (idx < end) {
            float h;
            if (stream == 0) {
                h = nhd[idx];
                g = d_gbid[idx];
            } else if (stream == 1) {
                h = fmaxf(nhd[d_es0[idx]], nhd[d_es1[idx]]) * d_esw[idx];
                g = d_eg[idx];
            } else {
                h = fmaxf(fmaxf(nhd[d_fs0[idx]], nhd[d_fs1[idx]]), nhd[d_fs2[idx]]) * d_fsw[idx];
                g = d_fg[idx];
            }
            hs = 50.f * h;
        } else {
            hs = 0.f; g = -1;
        }

        int g0  = __shfl_sync(0xffffffffu, g, 0);
        int g31 = __shfl_sync(0xffffffffu, g, 31);
        if (g0 == g31 && g0 >= 0) {
            // fast path: full batch, single graph (common: streams sorted by graph)
            if (g0 != gcur) {
                if (gcur >= 0) atomicAdd(&d_accS[(gcur * NBUMP + lane) * Dd + d], sign * acc);
                acc = 0.f; gcur = g0;
            }
            #pragma unroll
            for (int i = 0; i < 32; i++) {
                float t = __shfl_sync(0xffffffffu, hs, i);
                acc += tanha(cl - t);
            }
        } else {
            #pragma unroll
            for (int i = 0; i < 32; i++) {
                int   gi = __shfl_sync(0xffffffffu, g, i);
                float t  = __shfl_sync(0xffffffffu, hs, i);
                if (gi < 0) continue;           // warp-uniform predicate
                if (gi != gcur) {
                    if (gcur >= 0) atomicAdd(&d_accS[(gcur * NBUMP + lane) * Dd + d], sign * acc);
                    acc = 0.f; gcur = gi;
                }
                acc += tanha(cl - t);
            }
        }
    }
    if (gcur >= 0) atomicAdd(&d_accS[(gcur * NBUMP + lane) * Dd + d], sign * acc);
}

// ecc = 0.5*netcount(g) + 0.5*signed_tanh_sum; write flat region of output
__global__ void finalize_kernel(float* __restrict__ out) {
    int i = blockIdx.x * blockDim.x + threadIdx.x;
    if (i >= Gg * NBUMP * Dd) return;
    int g = i >> 11;  // / (NBUMP*Dd)
    out[Gg * NCLS + i] = 0.5f * (float)d_netc[g] + 0.5f * d_accS[i];
}

__global__ void mlp_kernel(const float* __restrict__ W1, const float* __restrict__ b1,
                           const float* __restrict__ W2, const float* __restrict__ b2,
                           float* __restrict__ out) {
    __shared__ float sflat[NBUMP * Dd];
    __shared__ float sh[HIDN];
    int g = blockIdx.x;
    const float* flat = out + Gg * NCLS + g * (NBUMP * Dd);
    for (int i = threadIdx.x; i < NBUMP * Dd; i += blockDim.x) sflat[i] = flat[i];
    __syncthreads();

    int warp = threadIdx.x >> 5, lane = threadIdx.x & 31;
    for (int hh = warp; hh < HIDN; hh += 8) {
        const float* wrow = W1 + hh * (NBUMP * Dd);
        float p = 0.f;
        #pragma unroll 8
        for (int k = lane; k < NBUMP * Dd; k += 32) p += wrow[k] * sflat[k];
        #pragma unroll
        for (int o = 16; o; o >>= 1) p += __shfl_down_sync(0xffffffffu, p, o);
        if (lane == 0) sh[hh] = fmaxf(p + b1[hh], 0.f);
    }
    __syncthreads();
    if (warp == 0) {
        for (int c = 0; c < NCLS; c++) {
            float p = 0.f;
            #pragma unroll
            for (int k = lane; k < HIDN; k += 32) p += W2[c * HIDN + k] * sh[k];
            #pragma unroll
            for (int o = 16; o; o >>= 1) p += __shfl_down_sync(0xffffffffu, p, o);
            if (lane == 0) out[g * NCLS + c] = p + b2[c];
        }
    }
}

// ---------------- launch ----------------
extern "C" void kernel_launch(void* const* d_in, const int* in_sizes, int n_in,
                              void* d_out, int out_size) {
    const float* x   = (const float*)d_in[0];
    const float* nw  = (const float*)d_in[1];
    const float* ew  = (const float*)d_in[2];
    const float* fw  = (const float*)d_in[3];
    const float* v   = (const float*)d_in[4];
    const float* W1  = (const float*)d_in[5];
    const float* b1  = (const float*)d_in[6];
    const float* W2  = (const float*)d_in[7];
    const float* b2  = (const float*)d_in[8];
    const int*   ei  = (const int*)d_in[9];    // int32 (JAX x64 disabled)
    const int*   fc  = (const int*)d_in[10];   // int32
    const int*   bid = (const int*)d_in[11];   // int32
    float* out = (float*)d_out;

    zero_kernel<<<(Gg * NBUMP * Dd + 255) / 256, 256>>>();
    p1_kernel<<<(Nn + 255) / 256, 256>>>(bid);
    nh_kernel<<<(Nn + 255) / 256, 256>>>(x, nw, v);
    hist_ef<<<(Ee + Ff + 255) / 256, 256>>>(ei, fc);
    scan_kernel<<<1, 32>>>();
    scatter_ef<<<(Ee + Ff + 255) / 256, 256>>>(ei, ew, fc, fw);

    dim3 mg((TOT_W + 7) / 8, Dd);
    main_kernel<<<mg, 256>>>();

    finalize_kernel<<<(Gg * NBUMP * Dd + 255) / 256, 256>>>(out);
    mlp_kernel<<<Gg, 256>>>(W1, b1, W2, b2, out);
}

// round 11
// speedup vs baseline: 1.1339x; 1.1339x over previous
#include <cuda_runtime.h>

#define Nn   16000
#define Ee   48000
#define Ff   32000
#define Gg   32
#define Dd   64
#define NBUMP 32
#define HIDN  256
#define NCLS  10
#define STRIP 256
#define NCHUNK 16              // Dd/4 direction chunks

#define NODE_W ((Nn + STRIP - 1) / STRIP)   // 63
#define EDGE_W ((Ee + STRIP - 1) / STRIP)   // 188
#define FACE_W ((Ff + STRIP - 1) / STRIP)   // 125
#define TOT_W  (NODE_W + EDGE_W + FACE_W)   // 376

// ---------------- scratch (static device globals) ----------------
__device__ float4 d_nh4[Nn * NCHUNK];     // node-major heights: [n][dchunk] -> 4 dirs
__device__ int4   d_epk[Ee];              // {e0, e1, g, w_bits} graph-sorted
__device__ int4   d_fpk[Ff];              // {f0, f1, f2, g} graph-sorted
__device__ float  d_fsw[Ff];
__device__ int    d_ncnt[Gg], d_ecnt[Gg], d_fcnt[Gg];
__device__ int    d_ecur[Gg], d_fcur[Gg];
__device__ int    d_netc[Gg];
__device__ float  d_accS[Gg * NBUMP * Dd];  // signed tanh sums [g][bump][d]

// ---------------- launch 1: node heights + zero all counters/acc ----------------
__global__ void nh_kernel(const float* __restrict__ x,
                          const float* __restrict__ nw,
                          const float* __restrict__ v) {
    __shared__ float sv[3 * Dd];
    if (threadIdx.x < 3 * Dd) sv[threadIdx.x] = v[threadIdx.x];
    __syncthreads();

    int tid = blockIdx.x * blockDim.x + threadIdx.x;
    int nthreads = gridDim.x * blockDim.x;
    // zero accumulators + counters (grid-stride)
    for (int i = tid; i < Gg * NBUMP * Dd; i += nthreads) d_accS[i] = 0.f;
    if (tid < Gg) { d_ncnt[tid] = 0; d_ecnt[tid] = 0; d_fcnt[tid] = 0; }

    int n = tid;
    if (n >= Nn) return;
    float x0 = x[3 * n], x1 = x[3 * n + 1], x2 = x[3 * n + 2];
    float w = nw[n];
    #pragma unroll
    for (int c = 0; c < NCHUNK; c++) {
        float4 h;
        int d = c * 4;
        h.x = w * (x0 * sv[d + 0] + x1 * sv[Dd + d + 0] + x2 * sv[2 * Dd + d + 0]);
        h.y = w * (x0 * sv[d + 1] + x1 * sv[Dd + d + 1] + x2 * sv[2 * Dd + d + 1]);
        h.z = w * (x0 * sv[d + 2] + x1 * sv[Dd + d + 2] + x2 * sv[2 * Dd + d + 2]);
        h.w = w * (x0 * sv[d + 3] + x1 * sv[Dd + d + 3] + x2 * sv[2 * Dd + d + 3]);
        d_nh4[n * NCHUNK + c] = h;
    }
}

// ---------------- launch 2: histograms via shared memory ----------------
__global__ void prep_kernel(const int* __restrict__ bid,
                            const int* __restrict__ ei,
                            const int* __restrict__ fc) {
    __shared__ int sn[Gg], se[Gg], sf[Gg];
    int t = threadIdx.x;
    if (t < Gg) { sn[t] = 0; se[t] = 0; sf[t] = 0; }
    __syncthreads();
    int stride = gridDim.x * blockDim.x;
    int i0 = blockIdx.x * blockDim.x + t;
    for (int i = i0; i < Nn; i += stride) atomicAdd(&sn[bid[i]], 1);
    for (int i = i0; i < Ee; i += stride) atomicAdd(&se[bid[ei[i]]], 1);
    for (int i = i0; i < Ff; i += stride) atomicAdd(&sf[bid[fc[i]]], 1);
    __syncthreads();
    if (t < Gg) {
        if (sn[t]) atomicAdd(&d_ncnt[t], sn[t]);
        if (se[t]) atomicAdd(&d_ecnt[t], se[t]);
        if (sf[t]) atomicAdd(&d_fcnt[t], sf[t]);
    }
}

// ---------------- launch 3: exclusive scan + Euler counts ----------------
__global__ void scan_kernel() {
    if (threadIdx.x == 0) {
        int ea = 0, fa = 0;
        for (int g = 0; g < Gg; g++) {
            d_ecur[g] = ea; ea += d_ecnt[g];
            d_fcur[g] = fa; fa += d_fcnt[g];
            d_netc[g] = d_ncnt[g] - d_ecnt[g] + d_fcnt[g];
        }
    }
}

// ---------------- launch 4: counting-sort scatter (graph-contiguous streams) ----------------
__global__ void scatter_kernel(const int* __restrict__ ei,
                               const float* __restrict__ ew,
                               const int* __restrict__ fc,
                               const float* __restrict__ fw,
                               const int* __restrict__ bid) {
    int i = blockIdx.x * blockDim.x + threadIdx.x;
    if (i < Ee) {
        int e0 = ei[i];
        int e1 = ei[Ee + i];
        int g = bid[e0];
        int pos = atomicAdd(&d_ecur[g], 1);
        d_epk[pos] = make_int4(e0, e1, g, __float_as_int(ew[i]));
    } else if (i < Ee + Ff) {
        int j = i - Ee;
        int f0 = fc[j];
        int f1 = fc[Ff + j];
        int f2 = fc[2 * Ff + j];
        int g = bid[f0];
        int pos = atomicAdd(&d_fcur[g], 1);
        d_fpk[pos] = make_int4(f0, f1, f2, g);
        d_fsw[pos] = fw[j];
    }
}

__device__ __forceinline__ float tanha(float z) {
    float r;
    asm("tanh.approx.f32 %0, %1;" : "=f"(r) : "f"(z));
    return r;
}

// ---------------- launch 5: main ECC accumulation ----------------
// lane = bump; 4 directions per warp-pass; register accumulation per (graph, bump, 4 dirs)
__global__ void __launch_bounds__(256) main_kernel(const int* __restrict__ bid) {
    const int dchunk = blockIdx.y;                 // 0..15
    const int warp = blockIdx.x * 8 + (threadIdx.x >> 5);
    const int lane = threadIdx.x & 31;
    if (warp >= TOT_W) return;

    int stream, w;
    if (warp < NODE_W)               { stream = 0; w = warp; }
    else if (warp < NODE_W + EDGE_W) { stream = 1; w = warp - NODE_W; }
    else                             { stream = 2; w = warp - NODE_W - EDGE_W; }

    const int cnt = (stream == 0) ? Nn : (stream == 1) ? Ee : Ff;
    const int begin = w * STRIP;
    const int end   = min(begin + STRIP, cnt);
    if (begin >= end) return;

    // tanh argument: 50*(lin[b] - h)
    const float cl   = 50.f * (-1.f + (2.f / 31.f) * (float)lane);
    const float sign = (stream == 1) ? -1.f : 1.f;

    float a0 = 0.f, a1 = 0.f, a2 = 0.f, a3 = 0.f;
    int gcur = -1;

    #define FLUSH() do { \
        float* p = &d_accS[(gcur * NBUMP + lane) * Dd + dchunk * 4]; \
        atomicAdd(p + 0, sign * a0); atomicAdd(p + 1, sign * a1); \
        atomicAdd(p + 2, sign * a2); atomicAdd(p + 3, sign * a3); \
        a0 = a1 = a2 = a3 = 0.f; } while (0)

    for (int base = begin; base < end; base += 32) {
        int idx = base + lane;
        float4 h; int g;
        if (idx < end) {
            if (stream == 0) {
                h = d_nh4[idx * NCHUNK + dchunk];
                g = bid[idx];
            } else if (stream == 1) {
                int4 e = d_epk[idx];
                float4 ha = d_nh4[e.x * NCHUNK + dchunk];
                float4 hb = d_nh4[e.y * NCHUNK + dchunk];
                float ww = __int_as_float(e.w);
                h.x = fmaxf(ha.x, hb.x) * ww;
                h.y = fmaxf(ha.y, hb.y) * ww;
                h.z = fmaxf(ha.z, hb.z) * ww;
                h.w = fmaxf(ha.w, hb.w) * ww;
                g = e.z;
            } else {
                int4 f = d_fpk[idx];
                float4 ha = d_nh4[f.x * NCHUNK + dchunk];
                float4 hb = d_nh4[f.y * NCHUNK + dchunk];
                float4 hc = d_nh4[f.z * NCHUNK + dchunk];
                float ww = d_fsw[idx];
                h.x = fmaxf(fmaxf(ha.x, hb.x), hc.x) * ww;
                h.y = fmaxf(fmaxf(ha.y, hb.y), hc.y) * ww;
                h.z = fmaxf(fmaxf(ha.z, hb.z), hc.z) * ww;
                h.w = fmaxf(fmaxf(ha.w, hb.w), hc.w) * ww;
                g = f.w;
            }
            h.x *= 50.f; h.y *= 50.f; h.z *= 50.f; h.w *= 50.f;
        } else {
            h = make_float4(0.f, 0.f, 0.f, 0.f); g = -1;
        }

        int g0  = __shfl_sync(0xffffffffu, g, 0);
        int g31 = __shfl_sync(0xffffffffu, g, 31);
        if (g0 == g31 && g0 >= 0) {
            if (g0 != gcur) {
                if (gcur >= 0) FLUSH();
                gcur = g0;
            }
            #pragma unroll
            for (int i = 0; i < 32; i++) {
                float t0 = __shfl_sync(0xffffffffu, h.x, i);
                float t1 = __shfl_sync(0xffffffffu, h.y, i);
                float t2 = __shfl_sync(0xffffffffu, h.z, i);
                float t3 = __shfl_sync(0xffffffffu, h.w, i);
                a0 += tanha(cl - t0);
                a1 += tanha(cl - t1);
                a2 += tanha(cl - t2);
                a3 += tanha(cl - t3);
            }
        } else {
            #pragma unroll 4
            for (int i = 0; i < 32; i++) {
                int   gi = __shfl_sync(0xffffffffu, g, i);
                float t0 = __shfl_sync(0xffffffffu, h.x, i);
                float t1 = __shfl_sync(0xffffffffu, h.y, i);
                float t2 = __shfl_sync(0xffffffffu, h.z, i);
                float t3 = __shfl_sync(0xffffffffu, h.w, i);
                if (gi < 0) continue;            // warp-uniform predicate
                if (gi != gcur) {
                    if (gcur >= 0) FLUSH();
                    gcur = gi;
                }
                a0 += tanha(cl - t0);
                a1 += tanha(cl - t1);
                a2 += tanha(cl - t2);
                a3 += tanha(cl - t3);
            }
        }
    }
    if (gcur >= 0) FLUSH();
    #undef FLUSH
}

// ---------------- launch 6: finalize ecc + MLP, fused ----------------
__global__ void mlp_kernel(const float* __restrict__ W1, const float* __restrict__ b1,
                           const float* __restrict__ W2, const float* __restrict__ b2,
                           float* __restrict__ out) {
    __shared__ float sflat[NBUMP * Dd];
    __shared__ float sh[HIDN];
    int g = blockIdx.x;
    float halfnet = 0.5f * (float)d_netc[g];
    float* flat_out = out + Gg * NCLS + g * (NBUMP * Dd);
    const float* acc = d_accS + g * (NBUMP * Dd);
    for (int i = threadIdx.x; i < NBUMP * Dd; i += blockDim.x) {
        float val = halfnet + 0.5f * acc[i];
        sflat[i] = val;
        flat_out[i] = val;
    }
    __syncthreads();

    int warp = threadIdx.x >> 5, lane = threadIdx.x & 31;
    for (int hh = warp; hh < HIDN; hh += 8) {
        const float* wrow = W1 + hh * (NBUMP * Dd);
        float p = 0.f;
        #pragma unroll 8
        for (int k = lane; k < NBUMP * Dd; k += 32) p += wrow[k] * sflat[k];
        #pragma unroll
        for (int o = 16; o; o >>= 1) p += __shfl_down_sync(0xffffffffu, p, o);
        if (lane == 0) sh[hh] = fmaxf(p + b1[hh], 0.f);
    }
    __syncthreads();
    if (warp == 0) {
        for (int c = 0; c < NCLS; c++) {
            float p = 0.f;
            #pragma unroll
            for (int k = lane; k < HIDN; k += 32) p += W2[c * HIDN + k] * sh[k];
            #pragma unroll
            for (int o = 16; o; o >>= 1) p += __shfl_down_sync(0xffffffffu, p, o);
            if (lane == 0) out[g * NCLS + c] = p + b2[c];
        }
    }
}

// ---------------- launch ----------------
extern "C" void kernel_launch(void* const* d_in, const int* in_sizes, int n_in,
                              void* d_out, int out_size) {
    const float* x   = (const float*)d_in[0];
    const float* nw  = (const float*)d_in[1];
    const float* ew  = (const float*)d_in[2];
    const float* fw  = (const float*)d_in[3];
    const float* v   = (const float*)d_in[4];
    const float* W1  = (const float*)d_in[5];
    const float* b1  = (const float*)d_in[6];
    const float* W2  = (const float*)d_in[7];
    const float* b2  = (const float*)d_in[8];
    const int*   ei  = (const int*)d_in[9];    // int32 (JAX x64 disabled)
    const int*   fc  = (const int*)d_in[10];
    const int*   bid = (const int*)d_in[11];
    float* out = (float*)d_out;

    nh_kernel<<<(Nn + 255) / 256, 256>>>(x, nw, v);
    prep_kernel<<<128, 256>>>(bid, ei, fc);
    scan_kernel<<<1, 32>>>();
    scatter_kernel<<<(Ee + Ff + 255) / 256, 256>>>(ei, ew, fc, fw, bid);

    dim3 mg((TOT_W + 7) / 8, NCHUNK);
    main_kernel<<<mg, 256>>>(bid);

    mlp_kernel<<<Gg, 256>>>(W1, b1, W2, b2, out);
}